// round 5
// baseline (speedup 1.0000x reference)
#include <cuda_runtime.h>
#include <cstdint>

// ---------------------------------------------------------------------------
// GCN layer on GB300 (compiled as plain compute_103 PTX -> no tcgen05; use
// legacy-path mma.sync tf32 tensor cores instead):
//   d[i]  = rsqrt(1 + #{j : A[i][j] > 1e-15})
//   g     = diag(d) @ (x @ W^T)                      [8192,256]
//   out   = relu( diag(d) @ (A @ g + g) )            [8192,256]
//   output buffer = [ out (8192*256 f32) | verbatim copy of A (8192^2 f32) ]
//
// K1: degrees + A copy (HBM stream)
// K2: fp32 SIMT linear (exact); writes g row-major (exact, for +I term)
//     and transposed+tf32-rounded (B operand of K3)
// K3: mma.sync m16n8k8 tf32 GEMM, 128x128 CTA tile, 4-stage cp.async pipe
// ---------------------------------------------------------------------------

#define EPSV 1e-15f

static constexpr int NN = 8192;   // nodes
static constexpr int DF = 256;    // feature dim (in == out)

// K3 tiling
static constexpr int BK = 32;                       // K elems per stage
static constexpr int NCHUNK = NN / BK;              // 256
static constexpr int STAGES = 4;
static constexpr int LDSS = 36;                     // smem row stride in floats (144B, 16B-aligned, conflict-free)
static constexpr int TILE_FLOATS  = 128 * LDSS;     // one 128x32 tile (padded)
static constexpr int STAGE_FLOATS = 2 * TILE_FLOATS;
static constexpr int SMEM_BYTES   = STAGES * STAGE_FLOATS * 4;  // 147456

// scratch (static device arrays: allocation-free)
__device__ __align__(128) float g_gT[(size_t)DF * NN];  // tf32-rounded g^T [256][8192]
__device__ __align__(128) float g_h [(size_t)NN * DF];  // exact g [8192][256]
__device__ float g_d[NN];

// ---------------------------------------------------------------------------
// PTX helpers (all plain sm_80+ PTX: safe for non-'a' targets)
// ---------------------------------------------------------------------------
__device__ __forceinline__ uint32_t smem_u32(const void* p) {
    uint32_t a;
    asm("{ .reg .u64 t; cvta.to.shared.u64 t, %1; cvt.u32.u64 %0, t; }"
        : "=r"(a) : "l"(p));
    return a;
}

__device__ __forceinline__ void cp_async16(uint32_t dst, const void* src) {
    asm volatile("cp.async.cg.shared.global [%0], [%1], 16;"
                 :: "r"(dst), "l"(src));
}
#define CP_COMMIT() asm volatile("cp.async.commit_group;" ::: "memory")
#define CP_WAIT2()  asm volatile("cp.async.wait_group 2;" ::: "memory")

__device__ __forceinline__ uint32_t f2tf32(float f) {
    uint32_t r;
    asm("cvt.rna.tf32.f32 %0, %1;" : "=r"(r) : "f"(f));
    return r;
}

__device__ __forceinline__ void mma_tf32(float* d, const uint32_t* a,
                                         const uint32_t* b) {
    asm volatile(
        "mma.sync.aligned.m16n8k8.row.col.f32.tf32.tf32.f32 "
        "{%0,%1,%2,%3}, {%4,%5,%6,%7}, {%8,%9}, {%0,%1,%2,%3};"
        : "+f"(d[0]), "+f"(d[1]), "+f"(d[2]), "+f"(d[3])
        : "r"(a[0]), "r"(a[1]), "r"(a[2]), "r"(a[3]),
          "r"(b[0]), "r"(b[1]));
}

// ---------------------------------------------------------------------------
// K1: degrees + verbatim A copy. One block per row: 256 threads x 8 float4.
// ---------------------------------------------------------------------------
__global__ void __launch_bounds__(256) k1_deg_copy(const float* __restrict__ A,
                                                   float* __restrict__ Acopy) {
    int row = blockIdx.x;
    const float4* src = reinterpret_cast<const float4*>(A + (size_t)row * NN);
    float4*       dst = reinterpret_cast<float4*>(Acopy + (size_t)row * NN);
    int cnt = 0;
    #pragma unroll
    for (int i = 0; i < 8; i++) {
        float4 v = src[threadIdx.x + i * 256];
        dst[threadIdx.x + i * 256] = v;
        cnt += (v.x > EPSV) + (v.y > EPSV) + (v.z > EPSV) + (v.w > EPSV);
    }
    #pragma unroll
    for (int o = 16; o > 0; o >>= 1) cnt += __shfl_down_sync(0xffffffffu, cnt, o);
    __shared__ int ws[8];
    if ((threadIdx.x & 31) == 0) ws[threadIdx.x >> 5] = cnt;
    __syncthreads();
    if (threadIdx.x == 0) {
        int t = 0;
        #pragma unroll
        for (int w = 0; w < 8; w++) t += ws[w];
        g_d[row] = rsqrtf(1.0f + (float)t);
    }
}

// ---------------------------------------------------------------------------
// K2: g[j][n] = d[j] * sum_k x[j][k] * W[n][k]  (exact fp32).
// Block = 64 j-rows; thread = one output feature n (0..255).
// Writes g_h exact (row-major) and g_gT tf32-rounded (transposed).
// ---------------------------------------------------------------------------
__global__ void __launch_bounds__(256) k2_linear(const float* __restrict__ x,
                                                 const float* __restrict__ W) {
    __shared__ float xs[64 * LDSS];     //  9216 B
    __shared__ float wsm[256 * LDSS];   // 36864 B
    __shared__ float ds[64];
    int tid = threadIdx.x;
    int j0 = blockIdx.x * 64;
    if (tid < 64) ds[tid] = g_d[j0 + tid];

    float acc[64];
    #pragma unroll
    for (int j = 0; j < 64; j++) acc[j] = 0.0f;

    for (int kc = 0; kc < 8; kc++) {
        int k0 = kc * 32;
        __syncthreads();
        #pragma unroll
        for (int i = 0; i < 8; i++) {
            int e = tid + i * 256;
            int j = e >> 5, k = e & 31;
            xs[j * LDSS + k] = x[(size_t)(j0 + j) * DF + k0 + k];
        }
        #pragma unroll
        for (int i = 0; i < 32; i++) {
            int e = tid + i * 256;
            int n = e >> 5, k = e & 31;
            wsm[n * LDSS + k] = W[(size_t)n * DF + k0 + k];
        }
        __syncthreads();
        #pragma unroll
        for (int k4 = 0; k4 < 8; k4++) {
            float4 w4 = *reinterpret_cast<const float4*>(&wsm[tid * LDSS + k4 * 4]);
            #pragma unroll
            for (int j = 0; j < 64; j++) {
                float4 x4 = *reinterpret_cast<const float4*>(&xs[j * LDSS + k4 * 4]);
                acc[j] = fmaf(x4.x, w4.x, acc[j]);
                acc[j] = fmaf(x4.y, w4.y, acc[j]);
                acc[j] = fmaf(x4.z, w4.z, acc[j]);
                acc[j] = fmaf(x4.w, w4.w, acc[j]);
            }
        }
    }
    float vals[64];
    #pragma unroll
    for (int j = 0; j < 64; j++) {
        float v = ds[j] * acc[j];
        g_h[(size_t)(j0 + j) * DF + tid] = v;             // exact (for +I term)
        vals[j] = __uint_as_float(f2tf32(v));             // pre-rounded B operand
    }
    float4* gt = reinterpret_cast<float4*>(g_gT + (size_t)tid * NN + j0);
    #pragma unroll
    for (int j4 = 0; j4 < 16; j4++) {
        float4 v;
        v.x = vals[j4 * 4 + 0]; v.y = vals[j4 * 4 + 1];
        v.z = vals[j4 * 4 + 2]; v.w = vals[j4 * 4 + 3];
        gt[j4] = v;
    }
}

// ---------------------------------------------------------------------------
// K3: out[i][c] = relu( d_i * ( sum_j A[i][j] * g[j][c] + g[i][c] ) )
// mma.sync tf32. CTA tile 128(i) x 128(c), K = 8192 in 256 chunks of 32.
// 8 warps (2x4): warp tile 64x32 = 4x4 m16n8 frags.
// ---------------------------------------------------------------------------
__device__ __forceinline__ void k3_stage_load(uint32_t sbase, int s,
                                              const float* __restrict__ aSrc,
                                              const float* __restrict__ bSrc,
                                              int tid) {
    uint32_t stA = sbase + (uint32_t)(s * STAGE_FLOATS * 4);
    uint32_t stB = stA + (uint32_t)(TILE_FLOATS * 4);
    #pragma unroll
    for (int i = 0; i < 4; i++) {            // A tile: 128 rows x 8 x 16B
        int e = tid + i * 256;
        int r = e >> 3, c = e & 7;
        cp_async16(stA + r * (LDSS * 4) + c * 16, aSrc + (size_t)r * NN + c * 4);
    }
    #pragma unroll
    for (int i = 0; i < 4; i++) {            // B tile: 128 rows x 8 x 16B
        int e = tid + i * 256;
        int r = e >> 3, c = e & 7;
        cp_async16(stB + r * (LDSS * 4) + c * 16, bSrc + (size_t)r * NN + c * 4);
    }
}

__global__ void __launch_bounds__(256, 1) k3_gemm(const float* __restrict__ Aop,
                                                  float* __restrict__ outp) {
    extern __shared__ float smem[];
    uint32_t sbase = smem_u32(smem);
    int tid  = threadIdx.x;
    int lane = tid & 31;
    int wid  = tid >> 5;
    int warp_m = wid >> 2;       // 0..1 -> m offset *64
    int warp_n = wid & 3;        // 0..3 -> n offset *32
    int m0 = blockIdx.x * 128;
    int c0 = blockIdx.y * 128;

    float acc[4][4][4];
    #pragma unroll
    for (int mi = 0; mi < 4; mi++)
        #pragma unroll
        for (int ni = 0; ni < 4; ni++)
            #pragma unroll
            for (int q = 0; q < 4; q++) acc[mi][ni][q] = 0.0f;

    const float* aBase = Aop  + (size_t)m0 * NN;
    const float* bBase = g_gT + (size_t)c0 * NN;

    // prologue: stages 0..2
    #pragma unroll
    for (int s = 0; s < STAGES - 1; s++) {
        k3_stage_load(sbase, s, aBase + s * BK, bBase + s * BK, tid);
        CP_COMMIT();
    }

    int arow = warp_m * 64 + (lane >> 2);     // A frag base row within tile
    int acol = lane & 3;                      // A/B frag base col within k-step
    int brow = warp_n * 32 + (lane >> 2);     // B frag base row within tile

    for (int kc = 0; kc < NCHUNK; kc++) {
        CP_WAIT2();            // stage kc complete (2 younger groups pending)
        __syncthreads();
        const float* As = smem + (kc & 3) * STAGE_FLOATS;
        const float* Bs = As + TILE_FLOATS;
        #pragma unroll
        for (int kk = 0; kk < 4; kk++) {
            int kb = kk * 8 + acol;
            uint32_t af[4][4];
            #pragma unroll
            for (int mi = 0; mi < 4; mi++) {
                const float* ap = As + (arow + mi * 16) * LDSS + kb;
                af[mi][0] = f2tf32(ap[0]);
                af[mi][1] = f2tf32(ap[8 * LDSS]);
                af[mi][2] = f2tf32(ap[4]);
                af[mi][3] = f2tf32(ap[8 * LDSS + 4]);
            }
            uint32_t bf[4][2];
            #pragma unroll
            for (int ni = 0; ni < 4; ni++) {
                const float* bp = Bs + (brow + ni * 8) * LDSS + kb;
                bf[ni][0] = __float_as_uint(bp[0]);   // pre-rounded in K2
                bf[ni][1] = __float_as_uint(bp[4]);
            }
            #pragma unroll
            for (int mi = 0; mi < 4; mi++)
                #pragma unroll
                for (int ni = 0; ni < 4; ni++)
                    mma_tf32(acc[mi][ni], af[mi], bf[ni]);
        }
        __syncthreads();
        int kl = kc + STAGES - 1;
        if (kl < NCHUNK)
            k3_stage_load(sbase, kl & 3, aBase + kl * BK, bBase + kl * BK, tid);
        CP_COMMIT();           // empty group at tail keeps accounting aligned
    }

    // epilogue: out = relu(d_i * (acc + g_i))
    #pragma unroll
    for (int mi = 0; mi < 4; mi++) {
        int r0 = m0 + warp_m * 64 + mi * 16 + (lane >> 2);
        int r1 = r0 + 8;
        float d0 = g_d[r0], d1 = g_d[r1];
        #pragma unroll
        for (int ni = 0; ni < 4; ni++) {
            int cc = c0 + warp_n * 32 + ni * 8 + (lane & 3) * 2;
            float2 gh0 = *reinterpret_cast<const float2*>(g_h + (size_t)r0 * DF + cc);
            float2 gh1 = *reinterpret_cast<const float2*>(g_h + (size_t)r1 * DF + cc);
            float2 v0, v1;
            v0.x = fmaxf(d0 * (acc[mi][ni][0] + gh0.x), 0.0f);
            v0.y = fmaxf(d0 * (acc[mi][ni][1] + gh0.y), 0.0f);
            v1.x = fmaxf(d1 * (acc[mi][ni][2] + gh1.x), 0.0f);
            v1.y = fmaxf(d1 * (acc[mi][ni][3] + gh1.y), 0.0f);
            *reinterpret_cast<float2*>(outp + (size_t)r0 * DF + cc) = v0;
            *reinterpret_cast<float2*>(outp + (size_t)r1 * DF + cc) = v1;
        }
    }
}

// ---------------------------------------------------------------------------
// launch
// ---------------------------------------------------------------------------
extern "C" void kernel_launch(void* const* d_in, const int* in_sizes, int n_in,
                              void* d_out, int out_size) {
    (void)in_sizes; (void)n_in; (void)out_size;
    const float* x = (const float*)d_in[0];
    const float* A = (const float*)d_in[1];
    const float* W = (const float*)d_in[2];
    float* out   = (float*)d_out;
    float* Acopy = out + (size_t)NN * DF;

    cudaFuncSetAttribute(k3_gemm, cudaFuncAttributeMaxDynamicSharedMemorySize,
                         SMEM_BYTES);

    k1_deg_copy<<<NN, 256>>>(A, Acopy);
    k2_linear<<<NN / 64, 256>>>(x, W);
    dim3 g3(NN / 128, DF / 128);
    k3_gemm<<<g3, 256, SMEM_BYTES>>>(A, out);
}

// round 7
// speedup vs baseline: 1.0633x; 1.0633x over previous
#include <cuda_runtime.h>
#include <cstdint>

// ---------------------------------------------------------------------------
// GCN layer on GB300 (plain compute_103 PTX -> legacy mma.sync tf32 path):
//   d[i]  = rsqrt(1 + #{j : A[i][j] > 1e-15})
//   g     = diag(d) @ (x @ W^T)                      [8192,256]
//   out   = relu( diag(d) @ (A @ g + g) )            [8192,256]
//   output buffer = [ out (8192*256 f32) | verbatim copy of A (8192^2 f32) ]
//
// K1: degrees only (A read once)
// K2: fp32 SIMT linear (exact); writes g_h exact + g_gT tf32-rounded with
//     (k,k+4)-paired column permutation (so K3 B-frags are single LDS.64)
// K3: mma.sync m16n8k8 tf32 GEMM, 128x128 CTA tile, 4-stage cp.async pipe;
//     ALSO writes the verbatim A copy from its staged smem tiles (saves a
//     full 256MB re-read vs doing the copy in K1).
// ---------------------------------------------------------------------------

#define EPSV 1e-15f

static constexpr int NN = 8192;   // nodes
static constexpr int DF = 256;    // feature dim (in == out)

// K3 tiling
static constexpr int BK = 32;                        // K elems per stage
static constexpr int NCHUNK = NN / BK;               // 256
static constexpr int STAGES = 4;
static constexpr int LDSA = 36;   // A smem row stride (floats): conflict-free LDS.32
static constexpr int LDSB = 40;   // B smem row stride (floats): conflict-free LDS.64
static constexpr int A_TILE_FLOATS = 128 * LDSA;     // 4608
static constexpr int B_TILE_FLOATS = 128 * LDSB;     // 5120
static constexpr int STAGE_FLOATS  = A_TILE_FLOATS + B_TILE_FLOATS;  // 9728
static constexpr int SMEM_BYTES    = STAGES * STAGE_FLOATS * 4;      // 155648

// scratch (static device arrays: allocation-free)
__device__ __align__(128) float g_gT[(size_t)DF * NN];  // tf32-rounded, k-paired g^T
__device__ __align__(128) float g_h [(size_t)NN * DF];  // exact g [8192][256]
__device__ float g_d[NN];

// ---------------------------------------------------------------------------
// PTX helpers (plain sm_80+ PTX only: safe for non-'a' target)
// ---------------------------------------------------------------------------
__device__ __forceinline__ uint32_t smem_u32(const void* p) {
    uint32_t a;
    asm("{ .reg .u64 t; cvta.to.shared.u64 t, %1; cvt.u32.u64 %0, t; }"
        : "=r"(a) : "l"(p));
    return a;
}

__device__ __forceinline__ void cp_async16(uint32_t dst, const void* src) {
    asm volatile("cp.async.cg.shared.global [%0], [%1], 16;"
                 :: "r"(dst), "l"(src));
}
#define CP_COMMIT() asm volatile("cp.async.commit_group;" ::: "memory")
#define CP_WAIT2()  asm volatile("cp.async.wait_group 2;" ::: "memory")

__device__ __forceinline__ uint32_t f2tf32(float f) {
    uint32_t r;
    asm("cvt.rna.tf32.f32 %0, %1;" : "=r"(r) : "f"(f));
    return r;
}

__device__ __forceinline__ void mma_tf32(float* d, const uint32_t* a,
                                         const uint32_t* b) {
    asm volatile(
        "mma.sync.aligned.m16n8k8.row.col.f32.tf32.tf32.f32 "
        "{%0,%1,%2,%3}, {%4,%5,%6,%7}, {%8,%9}, {%0,%1,%2,%3};"
        : "+f"(d[0]), "+f"(d[1]), "+f"(d[2]), "+f"(d[3])
        : "r"(a[0]), "r"(a[1]), "r"(a[2]), "r"(a[3]),
          "r"(b[0]), "r"(b[1]));
}

// ---------------------------------------------------------------------------
// K1: degrees only. One block per row: 256 threads x 8 float4 (read 256 MB).
// ---------------------------------------------------------------------------
__global__ void __launch_bounds__(256) k1_deg(const float* __restrict__ A) {
    int row = blockIdx.x;
    const float4* src = reinterpret_cast<const float4*>(A + (size_t)row * NN);
    int cnt = 0;
    #pragma unroll
    for (int i = 0; i < 8; i++) {
        float4 v = src[threadIdx.x + i * 256];
        cnt += (v.x > EPSV) + (v.y > EPSV) + (v.z > EPSV) + (v.w > EPSV);
    }
    #pragma unroll
    for (int o = 16; o > 0; o >>= 1) cnt += __shfl_down_sync(0xffffffffu, cnt, o);
    __shared__ int ws[8];
    if ((threadIdx.x & 31) == 0) ws[threadIdx.x >> 5] = cnt;
    __syncthreads();
    if (threadIdx.x == 0) {
        int t = 0;
        #pragma unroll
        for (int w = 0; w < 8; w++) t += ws[w];
        g_d[row] = rsqrtf(1.0f + (float)t);
    }
}

// ---------------------------------------------------------------------------
// K2: g[j][n] = d[j] * sum_k x[j][k] * W[n][k]  (exact fp32).
// Block = 64 j-rows; thread = one output feature n (0..255).
// Writes g_h exact; writes g_gT tf32-rounded + (k,k+4)-pair permuted:
//   within each 8-group, logical j -> physical 2*(j&3) + ((j>>2)&1).
// ---------------------------------------------------------------------------
__global__ void __launch_bounds__(256) k2_linear(const float* __restrict__ x,
                                                 const float* __restrict__ W) {
    __shared__ float xs[64 * LDSA];
    __shared__ float wsm[256 * LDSA];
    __shared__ float ds[64];
    int tid = threadIdx.x;
    int j0 = blockIdx.x * 64;
    if (tid < 64) ds[tid] = g_d[j0 + tid];

    float acc[64];
    #pragma unroll
    for (int j = 0; j < 64; j++) acc[j] = 0.0f;

    for (int kc = 0; kc < 8; kc++) {
        int k0 = kc * 32;
        __syncthreads();
        #pragma unroll
        for (int i = 0; i < 8; i++) {
            int e = tid + i * 256;
            int j = e >> 5, k = e & 31;
            xs[j * LDSA + k] = x[(size_t)(j0 + j) * DF + k0 + k];
        }
        #pragma unroll
        for (int i = 0; i < 32; i++) {
            int e = tid + i * 256;
            int n = e >> 5, k = e & 31;
            wsm[n * LDSA + k] = W[(size_t)n * DF + k0 + k];
        }
        __syncthreads();
        #pragma unroll
        for (int k4 = 0; k4 < 8; k4++) {
            float4 w4 = *reinterpret_cast<const float4*>(&wsm[tid * LDSA + k4 * 4]);
            #pragma unroll
            for (int j = 0; j < 64; j++) {
                float4 x4 = *reinterpret_cast<const float4*>(&xs[j * LDSA + k4 * 4]);
                acc[j] = fmaf(x4.x, w4.x, acc[j]);
                acc[j] = fmaf(x4.y, w4.y, acc[j]);
                acc[j] = fmaf(x4.z, w4.z, acc[j]);
                acc[j] = fmaf(x4.w, w4.w, acc[j]);
            }
        }
    }
    float vals[64];
    #pragma unroll
    for (int j = 0; j < 64; j++) {
        float v = ds[j] * acc[j];
        g_h[(size_t)(j0 + j) * DF + tid] = v;          // exact (for +I term)
        vals[j] = __uint_as_float(f2tf32(v));          // pre-rounded B operand
    }
    // permuted writes: group of 8 -> [v0,v4,v1,v5] [v2,v6,v3,v7]
    float4* gt = reinterpret_cast<float4*>(g_gT + (size_t)tid * NN + j0);
    #pragma unroll
    for (int q = 0; q < 8; q++) {
        const float* v = vals + q * 8;
        float4 lo, hi;
        lo.x = v[0]; lo.y = v[4]; lo.z = v[1]; lo.w = v[5];
        hi.x = v[2]; hi.y = v[6]; hi.z = v[3]; hi.w = v[7];
        gt[q * 2 + 0] = lo;
        gt[q * 2 + 1] = hi;
    }
}

// ---------------------------------------------------------------------------
// K3: out[i][c] = relu( d_i * ( sum_j A[i][j] * g[j][c] + g[i][c] ) )
// + writes verbatim A copy from staged smem (each of the 2 c-CTAs per m-tile
//   copies half the tile rows).
// ---------------------------------------------------------------------------
__device__ __forceinline__ void k3_stage_load(uint32_t sbase, int s,
                                              const float* __restrict__ aSrc,
                                              const float* __restrict__ bSrc,
                                              int tid) {
    uint32_t stA = sbase + (uint32_t)(s * STAGE_FLOATS * 4);
    uint32_t stB = stA + (uint32_t)(A_TILE_FLOATS * 4);
    #pragma unroll
    for (int i = 0; i < 4; i++) {            // A tile: 128 rows x 8 x 16B
        int e = tid + i * 256;
        int r = e >> 3, c = e & 7;
        cp_async16(stA + r * (LDSA * 4) + c * 16, aSrc + (size_t)r * NN + c * 4);
    }
    #pragma unroll
    for (int i = 0; i < 4; i++) {            // B tile: 128 rows x 8 x 16B
        int e = tid + i * 256;
        int r = e >> 3, c = e & 7;
        cp_async16(stB + r * (LDSB * 4) + c * 16, bSrc + (size_t)r * NN + c * 4);
    }
}

__global__ void __launch_bounds__(256, 1) k3_gemm(const float* __restrict__ Aop,
                                                  float* __restrict__ outp,
                                                  float* __restrict__ Acopy) {
    extern __shared__ float smem[];
    uint32_t sbase = smem_u32(smem);
    int tid  = threadIdx.x;
    int lane = tid & 31;
    int wid  = tid >> 5;
    int warp_m = wid >> 2;       // 0..1 -> m offset *64
    int warp_n = wid & 3;        // 0..3 -> n offset *32
    int m0 = blockIdx.x * 128;
    int c0 = blockIdx.y * 128;
    int copy_r0 = blockIdx.y * 64;   // this CTA copies tile rows [copy_r0, +64)

    float acc[4][4][4];
    #pragma unroll
    for (int mi = 0; mi < 4; mi++)
        #pragma unroll
        for (int ni = 0; ni < 4; ni++)
            #pragma unroll
            for (int q = 0; q < 4; q++) acc[mi][ni][q] = 0.0f;

    const float* aBase = Aop  + (size_t)m0 * NN;
    const float* bBase = g_gT + (size_t)c0 * NN;

    // prologue: stages 0..2
    #pragma unroll
    for (int s = 0; s < STAGES - 1; s++) {
        k3_stage_load(sbase, s, aBase + s * BK, bBase + s * BK, tid);
        CP_COMMIT();
    }

    int arow = warp_m * 64 + (lane >> 2);     // A frag base row within tile
    int acol = lane & 3;                      // A frag base col within k-step
    int brow = warp_n * 32 + (lane >> 2);     // B frag base row within tile
    // copy lane mapping: 2 float4 per thread per chunk over 64 rows x 8 chunks
    int cp_r = copy_r0 + (tid >> 3);          // rows copy_r0 .. +31 (i=0), +32..63 (i=1)
    int cp_c = (tid & 7) * 4;

    for (int kc = 0; kc < NCHUNK; kc++) {
        CP_WAIT2();            // stage kc complete (2 younger groups pending)
        __syncthreads();
        const float* As = smem + (kc & 3) * STAGE_FLOATS;
        const float* Bs = As + A_TILE_FLOATS;

        // verbatim A copy from smem (rows [copy_r0, copy_r0+64) of this tile)
        {
            float* dst = Acopy + (size_t)(m0 + cp_r) * NN + kc * BK + cp_c;
            const float* s0 = As + (cp_r) * LDSA + cp_c;
            float4 v0 = *reinterpret_cast<const float4*>(s0);
            float4 v1 = *reinterpret_cast<const float4*>(s0 + 32 * LDSA);
            *reinterpret_cast<float4*>(dst) = v0;
            *reinterpret_cast<float4*>(dst + (size_t)32 * NN) = v1;
        }

        #pragma unroll
        for (int kk = 0; kk < 4; kk++) {
            int kb = kk * 8 + acol;
            uint32_t af[4][4];
            #pragma unroll
            for (int mi = 0; mi < 4; mi++) {
                const float* ap = As + (arow + mi * 16) * LDSA + kb;
                af[mi][0] = f2tf32(ap[0]);
                af[mi][1] = f2tf32(ap[8 * LDSA]);
                af[mi][2] = f2tf32(ap[4]);
                af[mi][3] = f2tf32(ap[8 * LDSA + 4]);
            }
            uint32_t bf[4][2];
            #pragma unroll
            for (int ni = 0; ni < 4; ni++) {
                // permuted layout: (k, k+4) adjacent -> single 64-bit LDS
                const float2 bp = *reinterpret_cast<const float2*>(
                    Bs + (brow + ni * 8) * LDSB + kk * 8 + 2 * acol);
                bf[ni][0] = __float_as_uint(bp.x);
                bf[ni][1] = __float_as_uint(bp.y);
            }
            #pragma unroll
            for (int mi = 0; mi < 4; mi++)
                #pragma unroll
                for (int ni = 0; ni < 4; ni++)
                    mma_tf32(acc[mi][ni], af[mi], bf[ni]);
        }
        __syncthreads();
        int kl = kc + STAGES - 1;
        if (kl < NCHUNK)
            k3_stage_load(sbase, kl & 3, aBase + kl * BK, bBase + kl * BK, tid);
        CP_COMMIT();           // empty group at tail keeps accounting aligned
    }

    // epilogue: out = relu(d_i * (acc + g_i))
    #pragma unroll
    for (int mi = 0; mi < 4; mi++) {
        int r0 = m0 + warp_m * 64 + mi * 16 + (lane >> 2);
        int r1 = r0 + 8;
        float d0 = g_d[r0], d1 = g_d[r1];
        #pragma unroll
        for (int ni = 0; ni < 4; ni++) {
            int cc = c0 + warp_n * 32 + ni * 8 + (lane & 3) * 2;
            float2 gh0 = *reinterpret_cast<const float2*>(g_h + (size_t)r0 * DF + cc);
            float2 gh1 = *reinterpret_cast<const float2*>(g_h + (size_t)r1 * DF + cc);
            float2 v0, v1;
            v0.x = fmaxf(d0 * (acc[mi][ni][0] + gh0.x), 0.0f);
            v0.y = fmaxf(d0 * (acc[mi][ni][1] + gh0.y), 0.0f);
            v1.x = fmaxf(d1 * (acc[mi][ni][2] + gh1.x), 0.0f);
            v1.y = fmaxf(d1 * (acc[mi][ni][3] + gh1.y), 0.0f);
            *reinterpret_cast<float2*>(outp + (size_t)r0 * DF + cc) = v0;
            *reinterpret_cast<float2*>(outp + (size_t)r1 * DF + cc) = v1;
        }
    }
}

// ---------------------------------------------------------------------------
// launch
// ---------------------------------------------------------------------------
extern "C" void kernel_launch(void* const* d_in, const int* in_sizes, int n_in,
                              void* d_out, int out_size) {
    (void)in_sizes; (void)n_in; (void)out_size;
    const float* x = (const float*)d_in[0];
    const float* A = (const float*)d_in[1];
    const float* W = (const float*)d_in[2];
    float* out   = (float*)d_out;
    float* Acopy = out + (size_t)NN * DF;

    cudaFuncSetAttribute(k3_gemm, cudaFuncAttributeMaxDynamicSharedMemorySize,
                         SMEM_BYTES);

    k1_deg<<<NN, 256>>>(A);
    k2_linear<<<NN / 64, 256>>>(x, W);
    dim3 g3(NN / 128, DF / 128);
    k3_gemm<<<g3, 256, SMEM_BYTES>>>(A, out, Acopy);
}

// round 8
// speedup vs baseline: 1.2079x; 1.1360x over previous
#include <cuda_runtime.h>
#include <cstdint>

// ---------------------------------------------------------------------------
// GCN layer on GB300 (plain compute_103 PTX -> legacy mma.sync tf32 path):
//   d[i]  = rsqrt(1 + #{j : A[i][j] > 1e-15})
//   g     = diag(d) @ (x @ W^T)                      [8192,256]
//   out   = relu( diag(d) @ (A @ g + g) )            [8192,256]
//   output buffer = [ out (8192*256 f32) | verbatim copy of A (8192^2 f32) ]
//
// K1: degrees only (A read once)
// K2: fp32 SIMT linear (exact); writes g_h exact + g_gT tf32-rounded with
//     (k,k+4)-paired column permutation (so K3 B-frags are single LDS.64)
// K3: mma.sync m16n8k8 tf32 GEMM, 128x128 CTA tile, 4-stage cp.async pipe;
//     A operands fed as raw f32 (HW truncates to tf32 — saves 512 CVTs per
//     CTA-chunk); single syncthreads per chunk; also emits the verbatim
//     A copy from its staged smem tiles.
// ---------------------------------------------------------------------------

#define EPSV 1e-15f

static constexpr int NN = 8192;   // nodes
static constexpr int DF = 256;    // feature dim (in == out)

// K3 tiling
static constexpr int BK = 32;                        // K elems per stage
static constexpr int NCHUNK = NN / BK;               // 256
static constexpr int STAGES = 4;
static constexpr int LDSA = 36;   // A smem row stride (floats): conflict-free LDS.32
static constexpr int LDSB = 40;   // B smem row stride (floats): conflict-free LDS.64
static constexpr int A_TILE_FLOATS = 128 * LDSA;     // 4608
static constexpr int B_TILE_FLOATS = 128 * LDSB;     // 5120
static constexpr int STAGE_FLOATS  = A_TILE_FLOATS + B_TILE_FLOATS;  // 9728
static constexpr int SMEM_BYTES    = STAGES * STAGE_FLOATS * 4;      // 155648

// scratch (static device arrays: allocation-free)
__device__ __align__(128) float g_gT[(size_t)DF * NN];  // tf32-rounded, k-paired g^T
__device__ __align__(128) float g_h [(size_t)NN * DF];  // exact g [8192][256]
__device__ float g_d[NN];

// ---------------------------------------------------------------------------
// PTX helpers (plain sm_80+ PTX only: safe for non-'a' target)
// ---------------------------------------------------------------------------
__device__ __forceinline__ uint32_t smem_u32(const void* p) {
    uint32_t a;
    asm("{ .reg .u64 t; cvta.to.shared.u64 t, %1; cvt.u32.u64 %0, t; }"
        : "=r"(a) : "l"(p));
    return a;
}

__device__ __forceinline__ void cp_async16(uint32_t dst, const void* src) {
    asm volatile("cp.async.cg.shared.global [%0], [%1], 16;"
                 :: "r"(dst), "l"(src));
}
#define CP_COMMIT() asm volatile("cp.async.commit_group;" ::: "memory")
#define CP_WAIT2()  asm volatile("cp.async.wait_group 2;" ::: "memory")

__device__ __forceinline__ uint32_t f2tf32(float f) {
    uint32_t r;
    asm("cvt.rna.tf32.f32 %0, %1;" : "=r"(r) : "f"(f));
    return r;
}

__device__ __forceinline__ void mma_tf32(float* d, const uint32_t* a,
                                         const uint32_t* b) {
    asm volatile(
        "mma.sync.aligned.m16n8k8.row.col.f32.tf32.tf32.f32 "
        "{%0,%1,%2,%3}, {%4,%5,%6,%7}, {%8,%9}, {%0,%1,%2,%3};"
        : "+f"(d[0]), "+f"(d[1]), "+f"(d[2]), "+f"(d[3])
        : "r"(a[0]), "r"(a[1]), "r"(a[2]), "r"(a[3]),
          "r"(b[0]), "r"(b[1]));
}

// ---------------------------------------------------------------------------
// K1: degrees only. One block per row: 256 threads x 8 float4 (read 256 MB).
// ---------------------------------------------------------------------------
__global__ void __launch_bounds__(256) k1_deg(const float* __restrict__ A) {
    int row = blockIdx.x;
    const float4* src = reinterpret_cast<const float4*>(A + (size_t)row * NN);
    int cnt = 0;
    #pragma unroll
    for (int i = 0; i < 8; i++) {
        float4 v = src[threadIdx.x + i * 256];
        cnt += (v.x > EPSV) + (v.y > EPSV) + (v.z > EPSV) + (v.w > EPSV);
    }
    #pragma unroll
    for (int o = 16; o > 0; o >>= 1) cnt += __shfl_down_sync(0xffffffffu, cnt, o);
    __shared__ int ws[8];
    if ((threadIdx.x & 31) == 0) ws[threadIdx.x >> 5] = cnt;
    __syncthreads();
    if (threadIdx.x == 0) {
        int t = 0;
        #pragma unroll
        for (int w = 0; w < 8; w++) t += ws[w];
        g_d[row] = rsqrtf(1.0f + (float)t);
    }
}

// ---------------------------------------------------------------------------
// K2: g[j][n] = d[j] * sum_k x[j][k] * W[n][k]  (exact fp32).
// Block = 64 j-rows; thread = one output feature n (0..255).
// Writes g_h exact; writes g_gT tf32-rounded + (k,k+4)-pair permuted.
// ---------------------------------------------------------------------------
__global__ void __launch_bounds__(256) k2_linear(const float* __restrict__ x,
                                                 const float* __restrict__ W) {
    __shared__ float xs[64 * LDSA];
    __shared__ float wsm[256 * LDSA];
    __shared__ float ds[64];
    int tid = threadIdx.x;
    int j0 = blockIdx.x * 64;
    if (tid < 64) ds[tid] = g_d[j0 + tid];

    float acc[64];
    #pragma unroll
    for (int j = 0; j < 64; j++) acc[j] = 0.0f;

    for (int kc = 0; kc < 8; kc++) {
        int k0 = kc * 32;
        __syncthreads();
        #pragma unroll
        for (int i = 0; i < 8; i++) {
            int e = tid + i * 256;
            int j = e >> 5, k = e & 31;
            xs[j * LDSA + k] = x[(size_t)(j0 + j) * DF + k0 + k];
        }
        #pragma unroll
        for (int i = 0; i < 32; i++) {
            int e = tid + i * 256;
            int n = e >> 5, k = e & 31;
            wsm[n * LDSA + k] = W[(size_t)n * DF + k0 + k];
        }
        __syncthreads();
        #pragma unroll
        for (int k4 = 0; k4 < 8; k4++) {
            float4 w4 = *reinterpret_cast<const float4*>(&wsm[tid * LDSA + k4 * 4]);
            #pragma unroll
            for (int j = 0; j < 64; j++) {
                float4 x4 = *reinterpret_cast<const float4*>(&xs[j * LDSA + k4 * 4]);
                acc[j] = fmaf(x4.x, w4.x, acc[j]);
                acc[j] = fmaf(x4.y, w4.y, acc[j]);
                acc[j] = fmaf(x4.z, w4.z, acc[j]);
                acc[j] = fmaf(x4.w, w4.w, acc[j]);
            }
        }
    }
    float vals[64];
    #pragma unroll
    for (int j = 0; j < 64; j++) {
        float v = ds[j] * acc[j];
        g_h[(size_t)(j0 + j) * DF + tid] = v;          // exact (for +I term)
        vals[j] = __uint_as_float(f2tf32(v));          // pre-rounded B operand
    }
    // permuted writes: group of 8 -> [v0,v4,v1,v5] [v2,v6,v3,v7]
    float4* gt = reinterpret_cast<float4*>(g_gT + (size_t)tid * NN + j0);
    #pragma unroll
    for (int q = 0; q < 8; q++) {
        const float* v = vals + q * 8;
        float4 lo, hi;
        lo.x = v[0]; lo.y = v[4]; lo.z = v[1]; lo.w = v[5];
        hi.x = v[2]; hi.y = v[6]; hi.z = v[3]; hi.w = v[7];
        gt[q * 2 + 0] = lo;
        gt[q * 2 + 1] = hi;
    }
}

// ---------------------------------------------------------------------------
// K3: out[i][c] = relu( d_i * ( sum_j A[i][j] * g[j][c] + g[i][c] ) )
// + writes verbatim A copy from staged smem.
// ---------------------------------------------------------------------------
__device__ __forceinline__ void k3_stage_load(uint32_t sbase, int s,
                                              const float* __restrict__ aSrc,
                                              const float* __restrict__ bSrc,
                                              int tid) {
    uint32_t stA = sbase + (uint32_t)(s * STAGE_FLOATS * 4);
    uint32_t stB = stA + (uint32_t)(A_TILE_FLOATS * 4);
    #pragma unroll
    for (int i = 0; i < 4; i++) {            // A tile: 128 rows x 8 x 16B
        int e = tid + i * 256;
        int r = e >> 3, c = e & 7;
        cp_async16(stA + r * (LDSA * 4) + c * 16, aSrc + (size_t)r * NN + c * 4);
    }
    #pragma unroll
    for (int i = 0; i < 4; i++) {            // B tile: 128 rows x 8 x 16B
        int e = tid + i * 256;
        int r = e >> 3, c = e & 7;
        cp_async16(stB + r * (LDSB * 4) + c * 16, bSrc + (size_t)r * NN + c * 4);
    }
}

__global__ void __launch_bounds__(256, 1) k3_gemm(const float* __restrict__ Aop,
                                                  float* __restrict__ outp,
                                                  float* __restrict__ Acopy) {
    extern __shared__ float smem[];
    uint32_t sbase = smem_u32(smem);
    int tid  = threadIdx.x;
    int lane = tid & 31;
    int wid  = tid >> 5;
    int warp_m = wid >> 2;       // 0..1 -> m offset *64
    int warp_n = wid & 3;        // 0..3 -> n offset *32
    int m0 = blockIdx.x * 128;
    int c0 = blockIdx.y * 128;
    int copy_r0 = blockIdx.y * 64;   // this CTA copies tile rows [copy_r0, +64)

    float acc[4][4][4];
    #pragma unroll
    for (int mi = 0; mi < 4; mi++)
        #pragma unroll
        for (int ni = 0; ni < 4; ni++)
            #pragma unroll
            for (int q = 0; q < 4; q++) acc[mi][ni][q] = 0.0f;

    const float* aBase = Aop  + (size_t)m0 * NN;
    const float* bBase = g_gT + (size_t)c0 * NN;

    // prologue: stages 0..2
    #pragma unroll
    for (int s = 0; s < STAGES - 1; s++) {
        k3_stage_load(sbase, s, aBase + s * BK, bBase + s * BK, tid);
        CP_COMMIT();
    }

    int arow = warp_m * 64 + (lane >> 2);     // A frag base row within tile
    int acol = lane & 3;                      // A frag base col within k-step
    int brow = warp_n * 32 + (lane >> 2);     // B frag base row within tile
    int cp_r = copy_r0 + (tid >> 3);
    int cp_c = (tid & 7) * 4;

    for (int kc = 0; kc < NCHUNK; kc++) {
        CP_WAIT2();            // stage kc complete (2 younger groups pending)
        __syncthreads();       // (also retires all warps' reads of stage kc-1)
        const float* As = smem + (kc & 3) * STAGE_FLOATS;
        const float* Bs = As + A_TILE_FLOATS;

        // verbatim A copy from smem (rows [copy_r0, copy_r0+64) of this tile)
        {
            float* dst = Acopy + (size_t)(m0 + cp_r) * NN + kc * BK + cp_c;
            const float* s0 = As + (cp_r) * LDSA + cp_c;
            float4 v0 = *reinterpret_cast<const float4*>(s0);
            float4 v1 = *reinterpret_cast<const float4*>(s0 + 32 * LDSA);
            *reinterpret_cast<float4*>(dst) = v0;
            *reinterpret_cast<float4*>(dst + (size_t)32 * NN) = v1;
        }

        #pragma unroll
        for (int kk = 0; kk < 4; kk++) {
            int kb = kk * 8 + acol;
            uint32_t af[4][4];
            #pragma unroll
            for (int mi = 0; mi < 4; mi++) {
                // raw f32 bits: legacy HMMA truncates to tf32 in HW (no CVT)
                const uint32_t* ap = reinterpret_cast<const uint32_t*>(
                    As + (arow + mi * 16) * LDSA + kb);
                af[mi][0] = ap[0];
                af[mi][1] = ap[8 * LDSA];
                af[mi][2] = ap[4];
                af[mi][3] = ap[8 * LDSA + 4];
            }
            uint32_t bf[4][2];
            #pragma unroll
            for (int ni = 0; ni < 4; ni++) {
                // permuted layout: (k, k+4) adjacent -> single 64-bit LDS
                const float2 bp = *reinterpret_cast<const float2*>(
                    Bs + (brow + ni * 8) * LDSB + kk * 8 + 2 * acol);
                bf[ni][0] = __float_as_uint(bp.x);
                bf[ni][1] = __float_as_uint(bp.y);
            }
            #pragma unroll
            for (int mi = 0; mi < 4; mi++)
                #pragma unroll
                for (int ni = 0; ni < 4; ni++)
                    mma_tf32(acc[mi][ni], af[mi], bf[ni]);
        }
        // no second barrier: next load targets stage (kc-1)&3, already retired
        int kl = kc + STAGES - 1;
        if (kl < NCHUNK)
            k3_stage_load(sbase, kl & 3, aBase + kl * BK, bBase + kl * BK, tid);
        CP_COMMIT();           // empty group at tail keeps accounting aligned
    }

    // epilogue: out = relu(d_i * (acc + g_i))
    #pragma unroll
    for (int mi = 0; mi < 4; mi++) {
        int r0 = m0 + warp_m * 64 + mi * 16 + (lane >> 2);
        int r1 = r0 + 8;
        float d0 = g_d[r0], d1 = g_d[r1];
        #pragma unroll
        for (int ni = 0; ni < 4; ni++) {
            int cc = c0 + warp_n * 32 + ni * 8 + (lane & 3) * 2;
            float2 gh0 = *reinterpret_cast<const float2*>(g_h + (size_t)r0 * DF + cc);
            float2 gh1 = *reinterpret_cast<const float2*>(g_h + (size_t)r1 * DF + cc);
            float2 v0, v1;
            v0.x = fmaxf(d0 * (acc[mi][ni][0] + gh0.x), 0.0f);
            v0.y = fmaxf(d0 * (acc[mi][ni][1] + gh0.y), 0.0f);
            v1.x = fmaxf(d1 * (acc[mi][ni][2] + gh1.x), 0.0f);
            v1.y = fmaxf(d1 * (acc[mi][ni][3] + gh1.y), 0.0f);
            *reinterpret_cast<float2*>(outp + (size_t)r0 * DF + cc) = v0;
            *reinterpret_cast<float2*>(outp + (size_t)r1 * DF + cc) = v1;
        }
    }
}

// ---------------------------------------------------------------------------
// launch
// ---------------------------------------------------------------------------
extern "C" void kernel_launch(void* const* d_in, const int* in_sizes, int n_in,
                              void* d_out, int out_size) {
    (void)in_sizes; (void)n_in; (void)out_size;
    const float* x = (const float*)d_in[0];
    const float* A = (const float*)d_in[1];
    const float* W = (const float*)d_in[2];
    float* out   = (float*)d_out;
    float* Acopy = out + (size_t)NN * DF;

    cudaFuncSetAttribute(k3_gemm, cudaFuncAttributeMaxDynamicSharedMemorySize,
                         SMEM_BYTES);

    k1_deg<<<NN, 256>>>(A);
    k2_linear<<<NN / 64, 256>>>(x, W);
    dim3 g3(NN / 128, DF / 128);
    k3_gemm<<<g3, 256, SMEM_BYTES>>>(A, out, Acopy);
}

// round 9
// speedup vs baseline: 1.2686x; 1.0503x over previous
#include <cuda_runtime.h>
#include <cstdint>

// ---------------------------------------------------------------------------
// GCN layer on GB300 (plain compute_103 PTX -> legacy mma.sync tf32 path):
//   d[i]  = rsqrt(1 + #{j : A[i][j] > 1e-15})
//   g     = diag(d) @ (x @ W^T)                      [8192,256]
//   out   = relu( diag(d) @ (A @ g + g) )            [8192,256]
//   output buffer = [ out (8192*256 f32) | verbatim copy of A (8192^2 f32) ]
//
// K1: degrees only (A read once)
// K2: fp32 SIMT linear (exact); writes g_h exact + g_gT tf32-rounded with
//     16-group interleave [v0,v4,v8,v12][v1,v5,v9,v13]... so one LDS.128
//     in K3 serves two k-steps of B fragments.
// K3: mma.sync m16n8k8 tf32 GEMM, 128x128 CTA tile, 4-stage cp.async pipe;
//     A fragments via ldmatrix.x4 (1 instr per 16x8 frag), B via LDS.128,
//     raw-f32 A operands (HW tf32 truncation), single barrier per chunk,
//     verbatim A copy emitted from staged smem tiles.
// ---------------------------------------------------------------------------

#define EPSV 1e-15f

static constexpr int NN = 8192;   // nodes
static constexpr int DF = 256;    // feature dim (in == out)

// K3 tiling
static constexpr int BK = 32;                        // K elems per stage
static constexpr int NCHUNK = NN / BK;               // 256
static constexpr int STAGES = 4;
static constexpr int LDSA = 36;   // A smem row stride (floats): ldmatrix conflict-free
static constexpr int LDSB = 48;   // B smem row stride (floats): LDS.128 conflict-free
static constexpr int A_TILE_FLOATS = 128 * LDSA;     // 4608
static constexpr int B_TILE_FLOATS = 128 * LDSB;     // 6144
static constexpr int STAGE_FLOATS  = A_TILE_FLOATS + B_TILE_FLOATS;  // 10752
static constexpr int SMEM_BYTES    = STAGES * STAGE_FLOATS * 4;      // 172032

// scratch (static device arrays: allocation-free)
__device__ __align__(128) float g_gT[(size_t)DF * NN];  // tf32-rounded, 16-group interleaved g^T
__device__ __align__(128) float g_h [(size_t)NN * DF];  // exact g [8192][256]
__device__ float g_d[NN];

// ---------------------------------------------------------------------------
// PTX helpers (plain sm_80+ PTX only: safe for non-'a' target)
// ---------------------------------------------------------------------------
__device__ __forceinline__ uint32_t smem_u32(const void* p) {
    uint32_t a;
    asm("{ .reg .u64 t; cvta.to.shared.u64 t, %1; cvt.u32.u64 %0, t; }"
        : "=r"(a) : "l"(p));
    return a;
}

__device__ __forceinline__ void cp_async16(uint32_t dst, const void* src) {
    asm volatile("cp.async.cg.shared.global [%0], [%1], 16;"
                 :: "r"(dst), "l"(src));
}
#define CP_COMMIT() asm volatile("cp.async.commit_group;" ::: "memory")
#define CP_WAIT2()  asm volatile("cp.async.wait_group 2;" ::: "memory")

__device__ __forceinline__ uint32_t f2tf32(float f) {
    uint32_t r;
    asm("cvt.rna.tf32.f32 %0, %1;" : "=r"(r) : "f"(f));
    return r;
}

// ldmatrix.x4: four 8x8 b16 tiles == one 16x8 tf32 A fragment {a0,a1,a2,a3}
__device__ __forceinline__ void ldsm_x4(uint32_t* r, uint32_t addr) {
    asm volatile("ldmatrix.sync.aligned.m8n8.x4.shared.b16 {%0,%1,%2,%3}, [%4];"
                 : "=r"(r[0]), "=r"(r[1]), "=r"(r[2]), "=r"(r[3])
                 : "r"(addr));
}

__device__ __forceinline__ void mma_tf32(float* d, const uint32_t* a,
                                         const uint32_t* b) {
    asm volatile(
        "mma.sync.aligned.m16n8k8.row.col.f32.tf32.tf32.f32 "
        "{%0,%1,%2,%3}, {%4,%5,%6,%7}, {%8,%9}, {%0,%1,%2,%3};"
        : "+f"(d[0]), "+f"(d[1]), "+f"(d[2]), "+f"(d[3])
        : "r"(a[0]), "r"(a[1]), "r"(a[2]), "r"(a[3]),
          "r"(b[0]), "r"(b[1]));
}

// ---------------------------------------------------------------------------
// K1: degrees only. One block per row: 256 threads x 8 float4 (read 256 MB).
// ---------------------------------------------------------------------------
__global__ void __launch_bounds__(256) k1_deg(const float* __restrict__ A) {
    int row = blockIdx.x;
    const float4* src = reinterpret_cast<const float4*>(A + (size_t)row * NN);
    int cnt = 0;
    #pragma unroll
    for (int i = 0; i < 8; i++) {
        float4 v = src[threadIdx.x + i * 256];
        cnt += (v.x > EPSV) + (v.y > EPSV) + (v.z > EPSV) + (v.w > EPSV);
    }
    #pragma unroll
    for (int o = 16; o > 0; o >>= 1) cnt += __shfl_down_sync(0xffffffffu, cnt, o);
    __shared__ int ws[8];
    if ((threadIdx.x & 31) == 0) ws[threadIdx.x >> 5] = cnt;
    __syncthreads();
    if (threadIdx.x == 0) {
        int t = 0;
        #pragma unroll
        for (int w = 0; w < 8; w++) t += ws[w];
        g_d[row] = rsqrtf(1.0f + (float)t);
    }
}

// ---------------------------------------------------------------------------
// K2: g[j][n] = d[j] * sum_k x[j][k] * W[n][k]  (exact fp32).
// Block = 64 j-rows; thread = one output feature n (0..255).
// Writes g_h exact; writes g_gT tf32-rounded, 16-group interleaved:
//   within each 16-group, stored[a*4 + q] = v[a + 4q]  (a=0..3, q=0..3)
// ---------------------------------------------------------------------------
__global__ void __launch_bounds__(256) k2_linear(const float* __restrict__ x,
                                                 const float* __restrict__ W) {
    __shared__ float xs[64 * LDSA];
    __shared__ float wsm[256 * LDSA];
    __shared__ float ds[64];
    int tid = threadIdx.x;
    int j0 = blockIdx.x * 64;
    if (tid < 64) ds[tid] = g_d[j0 + tid];

    float acc[64];
    #pragma unroll
    for (int j = 0; j < 64; j++) acc[j] = 0.0f;

    for (int kc = 0; kc < 8; kc++) {
        int k0 = kc * 32;
        __syncthreads();
        #pragma unroll
        for (int i = 0; i < 8; i++) {
            int e = tid + i * 256;
            int j = e >> 5, k = e & 31;
            xs[j * LDSA + k] = x[(size_t)(j0 + j) * DF + k0 + k];
        }
        #pragma unroll
        for (int i = 0; i < 32; i++) {
            int e = tid + i * 256;
            int n = e >> 5, k = e & 31;
            wsm[n * LDSA + k] = W[(size_t)n * DF + k0 + k];
        }
        __syncthreads();
        #pragma unroll
        for (int k4 = 0; k4 < 8; k4++) {
            float4 w4 = *reinterpret_cast<const float4*>(&wsm[tid * LDSA + k4 * 4]);
            #pragma unroll
            for (int j = 0; j < 64; j++) {
                float4 x4 = *reinterpret_cast<const float4*>(&xs[j * LDSA + k4 * 4]);
                acc[j] = fmaf(x4.x, w4.x, acc[j]);
                acc[j] = fmaf(x4.y, w4.y, acc[j]);
                acc[j] = fmaf(x4.z, w4.z, acc[j]);
                acc[j] = fmaf(x4.w, w4.w, acc[j]);
            }
        }
    }
    float vals[64];
    #pragma unroll
    for (int j = 0; j < 64; j++) {
        float v = ds[j] * acc[j];
        g_h[(size_t)(j0 + j) * DF + tid] = v;          // exact (for +I term)
        vals[j] = __uint_as_float(f2tf32(v));          // pre-rounded B operand
    }
    // 16-group interleave: stored[a*4+q] = v[a+4q]
    float4* gt = reinterpret_cast<float4*>(g_gT + (size_t)tid * NN + j0);
    #pragma unroll
    for (int q16 = 0; q16 < 4; q16++) {
        const float* v = vals + q16 * 16;
        #pragma unroll
        for (int a = 0; a < 4; a++) {
            float4 w;
            w.x = v[a]; w.y = v[a + 4]; w.z = v[a + 8]; w.w = v[a + 12];
            gt[q16 * 4 + a] = w;
        }
    }
}

// ---------------------------------------------------------------------------
// K3: out[i][c] = relu( d_i * ( sum_j A[i][j] * g[j][c] + g[i][c] ) )
// + writes verbatim A copy from staged smem.
// ---------------------------------------------------------------------------
__device__ __forceinline__ void k3_stage_load(uint32_t sbase, int s,
                                              const float* __restrict__ aSrc,
                                              const float* __restrict__ bSrc,
                                              int tid) {
    uint32_t stA = sbase + (uint32_t)(s * STAGE_FLOATS * 4);
    uint32_t stB = stA + (uint32_t)(A_TILE_FLOATS * 4);
    #pragma unroll
    for (int i = 0; i < 4; i++) {            // A tile: 128 rows x 8 x 16B
        int e = tid + i * 256;
        int r = e >> 3, c = e & 7;
        cp_async16(stA + r * (LDSA * 4) + c * 16, aSrc + (size_t)r * NN + c * 4);
    }
    #pragma unroll
    for (int i = 0; i < 4; i++) {            // B tile: 128 rows x 8 x 16B
        int e = tid + i * 256;
        int r = e >> 3, c = e & 7;
        cp_async16(stB + r * (LDSB * 4) + c * 16, bSrc + (size_t)r * NN + c * 4);
    }
}

__global__ void __launch_bounds__(256, 1) k3_gemm(const float* __restrict__ Aop,
                                                  float* __restrict__ outp,
                                                  float* __restrict__ Acopy) {
    extern __shared__ float smem[];
    uint32_t sbase = smem_u32(smem);
    int tid  = threadIdx.x;
    int lane = tid & 31;
    int wid  = tid >> 5;
    int warp_m = wid >> 2;       // 0..1 -> m offset *64
    int warp_n = wid & 3;        // 0..3 -> n offset *32
    int m0 = blockIdx.x * 128;
    int c0 = blockIdx.y * 128;
    int copy_r0 = blockIdx.y * 64;   // this CTA copies tile rows [copy_r0, +64)

    float acc[4][4][4];
    #pragma unroll
    for (int mi = 0; mi < 4; mi++)
        #pragma unroll
        for (int ni = 0; ni < 4; ni++)
            #pragma unroll
            for (int q = 0; q < 4; q++) acc[mi][ni][q] = 0.0f;

    const float* aBase = Aop  + (size_t)m0 * NN;
    const float* bBase = g_gT + (size_t)c0 * NN;

    // prologue: stages 0..2
    #pragma unroll
    for (int s = 0; s < STAGES - 1; s++) {
        k3_stage_load(sbase, s, aBase + s * BK, bBase + s * BK, tid);
        CP_COMMIT();
    }

    // ldmatrix lane mapping: tiles {rows..+7}, {rows+8..}, {cols+4}, {both}
    int lm_row = ((lane >> 3) & 1) * 8 + (lane & 7);   // 0..15
    int lm_col = (lane >> 4) * 4;                      // 0 or 4 (floats)
    uint32_t a_lm_byte = (uint32_t)(((warp_m * 64 + lm_row) * LDSA + lm_col) * 4);
    // B LDS.128 lane mapping: row = brow + (lane>>2), float4 slot = lane&3
    uint32_t b_ld_f = (uint32_t)((warp_n * 32 + (lane >> 2)) * LDSB + (lane & 3) * 4);
    int cp_r = copy_r0 + (tid >> 3);
    int cp_c = (tid & 7) * 4;

    for (int kc = 0; kc < NCHUNK; kc++) {
        CP_WAIT2();            // stage kc complete (2 younger groups pending)
        __syncthreads();       // (also retires all warps' reads of stage kc-1)
        uint32_t stA = sbase + (uint32_t)((kc & 3) * STAGE_FLOATS * 4);
        const float* As = smem + (kc & 3) * STAGE_FLOATS;
        const float* Bs = As + A_TILE_FLOATS;

        // verbatim A copy from smem (rows [copy_r0, copy_r0+64) of this tile)
        {
            float* dst = Acopy + (size_t)(m0 + cp_r) * NN + kc * BK + cp_c;
            const float* s0 = As + (cp_r) * LDSA + cp_c;
            float4 v0 = *reinterpret_cast<const float4*>(s0);
            float4 v1 = *reinterpret_cast<const float4*>(s0 + 32 * LDSA);
            *reinterpret_cast<float4*>(dst) = v0;
            *reinterpret_cast<float4*>(dst + (size_t)32 * NN) = v1;
        }

        #pragma unroll
        for (int kh = 0; kh < 2; kh++) {       // two 16-k halves
            // one LDS.128 per ni covers both k-steps of this half
            float4 bq[4];
            #pragma unroll
            for (int ni = 0; ni < 4; ni++)
                bq[ni] = *reinterpret_cast<const float4*>(
                    Bs + b_ld_f + ni * 8 * LDSB + kh * 16);
            #pragma unroll
            for (int kj = 0; kj < 2; kj++) {   // kk = kh*2 + kj
                uint32_t af[4][4];
                uint32_t abase = stA + a_lm_byte + (uint32_t)((kh * 2 + kj) * 32);
                #pragma unroll
                for (int mi = 0; mi < 4; mi++)
                    ldsm_x4(af[mi], abase + (uint32_t)(mi * 16 * LDSA * 4));
                #pragma unroll
                for (int mi = 0; mi < 4; mi++)
                    #pragma unroll
                    for (int ni = 0; ni < 4; ni++) {
                        uint32_t bf[2];
                        bf[0] = __float_as_uint(kj ? bq[ni].z : bq[ni].x);
                        bf[1] = __float_as_uint(kj ? bq[ni].w : bq[ni].y);
                        mma_tf32(acc[mi][ni], af[mi], bf);
                    }
            }
        }
        // no second barrier: next load targets stage (kc-1)&3, already retired
        int kl = kc + STAGES - 1;
        if (kl < NCHUNK)
            k3_stage_load(sbase, kl & 3, aBase + kl * BK, bBase + kl * BK, tid);
        CP_COMMIT();           // empty group at tail keeps accounting aligned
    }

    // epilogue: out = relu(d_i * (acc + g_i))
    #pragma unroll
    for (int mi = 0; mi < 4; mi++) {
        int r0 = m0 + warp_m * 64 + mi * 16 + (lane >> 2);
        int r1 = r0 + 8;
        float d0 = g_d[r0], d1 = g_d[r1];
        #pragma unroll
        for (int ni = 0; ni < 4; ni++) {
            int cc = c0 + warp_n * 32 + ni * 8 + (lane & 3) * 2;
            float2 gh0 = *reinterpret_cast<const float2*>(g_h + (size_t)r0 * DF + cc);
            float2 gh1 = *reinterpret_cast<const float2*>(g_h + (size_t)r1 * DF + cc);
            float2 v0, v1;
            v0.x = fmaxf(d0 * (acc[mi][ni][0] + gh0.x), 0.0f);
            v0.y = fmaxf(d0 * (acc[mi][ni][1] + gh0.y), 0.0f);
            v1.x = fmaxf(d1 * (acc[mi][ni][2] + gh1.x), 0.0f);
            v1.y = fmaxf(d1 * (acc[mi][ni][3] + gh1.y), 0.0f);
            *reinterpret_cast<float2*>(outp + (size_t)r0 * DF + cc) = v0;
            *reinterpret_cast<float2*>(outp + (size_t)r1 * DF + cc) = v1;
        }
    }
}

// ---------------------------------------------------------------------------
// launch
// ---------------------------------------------------------------------------
extern "C" void kernel_launch(void* const* d_in, const int* in_sizes, int n_in,
                              void* d_out, int out_size) {
    (void)in_sizes; (void)n_in; (void)out_size;
    const float* x = (const float*)d_in[0];
    const float* A = (const float*)d_in[1];
    const float* W = (const float*)d_in[2];
    float* out   = (float*)d_out;
    float* Acopy = out + (size_t)NN * DF;

    cudaFuncSetAttribute(k3_gemm, cudaFuncAttributeMaxDynamicSharedMemorySize,
                         SMEM_BYTES);

    k1_deg<<<NN, 256>>>(A);
    k2_linear<<<NN / 64, 256>>>(x, W);
    dim3 g3(NN / 128, DF / 128);
    k3_gemm<<<g3, 256, SMEM_BYTES>>>(A, out, Acopy);
}